// round 9
// baseline (speedup 1.0000x reference)
#include <cuda_runtime.h>

// Problem constants (from reference_code)
#define Hn    50000
#define INn   50000
#define NNZn  800000
#define Bn    8
#define Tn    32

#define NB    ((Hn + 255) / 256)   // 196 scan blocks per matrix

// step kernel: 64 rows per block, single wave
#define STEP_ROWS_PER_BLOCK 64
#define STEP_GRID ((Hn + STEP_ROWS_PER_BLOCK - 1) / STEP_ROWS_PER_BLOCK)  // 782

// ---------------- device scratch (static globals; no runtime allocation) ----
__device__ float g_xT[(size_t)Tn * INn * Bn];      // x transposed -> (T, IN, B)
__device__ float g_ihpre[(size_t)Tn * Hn * Bn];    // ih spmm + bias, (T, H, B)
__device__ float g_h[2][Hn * Bn];                  // ping-pong hidden state (H, B)
__device__ int   g_rowptr[2][Hn + 1];              // [0]=hh, [1]=ih
__device__ int   g_cnt[2][Hn];
__device__ int   g_cur[2][Hn];
__device__ int   g_bsum[2][256];
__device__ int2  g_pairs[2][NNZn];                 // {col, float_as_int(val)}

// ---------------- preprocessing -------------------------------------------

__global__ void init_kernel() {
    int i = blockIdx.x * blockDim.x + threadIdx.x;
    if (i < Hn * Bn) g_h[0][i] = 0.0f;
    if (i < Hn) { g_cnt[0][i] = 0; g_cnt[1][i] = 0; }
}

// fused histogram over both matrices (gridDim.y selects matrix)
__global__ void hist_kernel(const int* __restrict__ hh_idx,
                            const int* __restrict__ ih_idx) {
    int j = blockIdx.x * blockDim.x + threadIdx.x;
    int m = blockIdx.y;
    if (j >= NNZn) return;
    const int* rows = m ? ih_idx : hh_idx;
    atomicAdd(&g_cnt[m][rows[j]], 1);
}

// phase 1: per-block inclusive scan of 256 counts
__global__ void scan1_kernel() {
    int m = blockIdx.y;
    int i = blockIdx.x * 256 + threadIdx.x;
    int v = (i < Hn) ? g_cnt[m][i] : 0;
    int lane = threadIdx.x & 31, w = threadIdx.x >> 5;
    int x = v;
#pragma unroll
    for (int o = 1; o < 32; o <<= 1) {
        int y = __shfl_up_sync(~0u, x, o);
        if (lane >= o) x += y;
    }
    __shared__ int wsum[8];
    if (lane == 31) wsum[w] = x;
    __syncthreads();
    if (w == 0 && lane < 8) {
        int y = wsum[lane];
#pragma unroll
        for (int o = 1; o < 8; o <<= 1) {
            int z = __shfl_up_sync(0xffu, y, o);
            if (lane >= o) y += z;
        }
        wsum[lane] = y;
    }
    __syncthreads();
    int incl = x + (w > 0 ? wsum[w - 1] : 0);
    if (i < Hn) g_rowptr[m][i] = incl - v;          // local exclusive
    if (threadIdx.x == 255) g_bsum[m][blockIdx.x] = incl;
}

// phase 2: scan the (<=256) block sums
__global__ void scan2_kernel() {
    int m = blockIdx.y;
    int t = threadIdx.x;
    int v = (t < NB) ? g_bsum[m][t] : 0;
    int lane = t & 31, w = t >> 5;
    int x = v;
#pragma unroll
    for (int o = 1; o < 32; o <<= 1) {
        int y = __shfl_up_sync(~0u, x, o);
        if (lane >= o) x += y;
    }
    __shared__ int wsum[8];
    if (lane == 31) wsum[w] = x;
    __syncthreads();
    if (w == 0 && lane < 8) {
        int y = wsum[lane];
#pragma unroll
        for (int o = 1; o < 8; o <<= 1) {
            int z = __shfl_up_sync(0xffu, y, o);
            if (lane >= o) y += z;
        }
        wsum[lane] = y;
    }
    __syncthreads();
    int incl = x + (w > 0 ? wsum[w - 1] : 0);
    if (t < NB) g_bsum[m][t] = incl - v;
    if (t == 255) g_rowptr[m][Hn] = incl;           // total nnz
}

// phase 3: add block offsets; materialize rowptr + scatter cursor
__global__ void scan3_kernel() {
    int m = blockIdx.y;
    int i = blockIdx.x * 256 + threadIdx.x;
    if (i >= Hn) return;
    int r = g_rowptr[m][i] + g_bsum[m][blockIdx.x];
    g_rowptr[m][i] = r;
    g_cur[m][i]    = r;
}

// fused scatter into CSR pair arrays (gridDim.y selects matrix)
__global__ void scatter_kernel(const int* __restrict__ hh_idx,
                               const float* __restrict__ hh_vals,
                               const int* __restrict__ ih_idx,
                               const float* __restrict__ ih_vals) {
    int j = blockIdx.x * blockDim.x + threadIdx.x;
    int m = blockIdx.y;
    if (j >= NNZn) return;
    const int*   idx  = m ? ih_idx  : hh_idx;
    const float* vals = m ? ih_vals : hh_vals;
    int r = idx[j];
    int c = idx[NNZn + j];
    int p = atomicAdd(&g_cur[m][r], 1);
    g_pairs[m][p] = make_int2(c, __float_as_int(vals[j]));
}

// x (B, T, IN) -> g_xT (T, IN, B)
__global__ void transpose_kernel(const float* __restrict__ x) {
    int idx = blockIdx.x * blockDim.x + threadIdx.x;   // over T*IN
    if (idx >= Tn * INn) return;
    int t = idx / INn;
    int c = idx - t * INn;
    float v[Bn];
#pragma unroll
    for (int b = 0; b < Bn; ++b)
        v[b] = x[(size_t)b * Tn * INn + (size_t)t * INn + c];
    float4* dst = reinterpret_cast<float4*>(&g_xT[(size_t)idx * Bn]);
    dst[0] = make_float4(v[0], v[1], v[2], v[3]);
    dst[1] = make_float4(v[4], v[5], v[6], v[7]);
}

// ---------------- main compute ---------------------------------------------

// ih_pre[t, r, b] = bias[r] + sum_j ih_val[j] * xT[t, col[j], b]
// 8 threads per row task (thread = batch lane); all 32 timesteps accumulated
// in registers so each CSR pair is read exactly once. (L2-roofline bound.)
__global__ void ih_kernel(const float* __restrict__ bias) {
    int g = blockIdx.x * 32 + (threadIdx.x >> 3);      // row
    if (g >= Hn) return;
    int b = threadIdx.x & 7;
    float bv = bias[g];
    float acc[Tn];
#pragma unroll
    for (int t = 0; t < Tn; ++t) acc[t] = bv;
    int jb = g_rowptr[1][g];
    int je = g_rowptr[1][g + 1];
    for (int j = jb; j < je; ++j) {
        int2 p = g_pairs[1][j];
        float v = __int_as_float(p.y);
        const float* xp = g_xT + (size_t)p.x * Bn + b;
#pragma unroll
        for (int t = 0; t < Tn; ++t)
            acc[t] += v * xp[(size_t)t * INn * Bn];
    }
#pragma unroll
    for (int t = 0; t < Tn; ++t)
        g_ihpre[((size_t)t * Hn + g) * Bn + b] = acc[t];
}

// one recurrence step, SINGLE-WAVE grid (782 blocks): each block covers 64
// rows, each warp 8 rows, each thread 2 rows with DUAL accumulators processed
// in one jointly-unrolled loop (one latency chain, 2x MLP).
template <bool LAST>
__global__ void __launch_bounds__(256)
step_kernel(const float* __restrict__ hprev,
            float* __restrict__ hnext,
            const float* __restrict__ ihpre_t,
            float* __restrict__ out_t) {   // d_out + t*H
    const int warp = threadIdx.x >> 5;                     // 0..7
    const int sub  = (threadIdx.x >> 3) & 3;               // 0..3
    const int b    = threadIdx.x & 7;                      // batch lane
    const int base = blockIdx.x * STEP_ROWS_PER_BLOCK + warp * 8;
    const int g0 = base + sub;
    const int g1 = base + 4 + sub;
    const bool v0 = g0 < Hn, v1 = g1 < Hn;

    float acc0 = v0 ? ihpre_t[g0 * Bn + b] : 0.0f;
    float acc1 = v1 ? ihpre_t[g1 * Bn + b] : 0.0f;
    int jb0 = 0, je0 = 0, jb1 = 0, je1 = 0;
    if (v0) { jb0 = g_rowptr[0][g0]; je0 = g_rowptr[0][g0 + 1]; }
    if (v1) { jb1 = g_rowptr[0][g1]; je1 = g_rowptr[0][g1 + 1]; }
    const int n0 = je0 - jb0, n1 = je1 - jb1;
    const int nc = n0 < n1 ? n0 : n1;

#pragma unroll 2
    for (int k = 0; k < nc; ++k) {
        int2 p0 = g_pairs[0][jb0 + k];
        int2 p1 = g_pairs[0][jb1 + k];
        acc0 += __int_as_float(p0.y) * hprev[p0.x * Bn + b];
        acc1 += __int_as_float(p1.y) * hprev[p1.x * Bn + b];
    }
#pragma unroll 2
    for (int k = nc; k < n0; ++k) {
        int2 p = g_pairs[0][jb0 + k];
        acc0 += __int_as_float(p.y) * hprev[p.x * Bn + b];
    }
#pragma unroll 2
    for (int k = nc; k < n1; ++k) {
        int2 p = g_pairs[0][jb1 + k];
        acc1 += __int_as_float(p.y) * hprev[p.x * Bn + b];
    }

    if (v0) {
        float hv = tanhf(acc0);
        if (!LAST) hnext[g0 * Bn + b] = hv;
        out_t[(size_t)b * Tn * Hn + g0] = hv;   // out layout (B, T, H)
    }
    if (v1) {
        float hv = tanhf(acc1);
        if (!LAST) hnext[g1 * Bn + b] = hv;
        out_t[(size_t)b * Tn * Hn + g1] = hv;
    }
}

// ---------------- launch ----------------------------------------------------

extern "C" void kernel_launch(void* const* d_in, const int* in_sizes, int n_in,
                              void* d_out, int out_size) {
    const float* x        = (const float*)d_in[0];   // (B, T, IN)
    const float* hh_vals  = (const float*)d_in[1];   // (NNZ,)
    const float* hh_bias  = (const float*)d_in[2];   // (H, 1)
    const float* ih_vals  = (const float*)d_in[3];   // (NNZ,)
    const int*   hh_idx   = (const int*)d_in[4];     // (2, NNZ): rows then cols
    const int*   ih_idx   = (const int*)d_in[5];     // (2, NNZ)
    float*       out      = (float*)d_out;           // (B, T, H)

    float *ihpre_p, *h_p;
    cudaGetSymbolAddress((void**)&ihpre_p, g_ihpre);
    cudaGetSymbolAddress((void**)&h_p,     g_h);

    const int TPB = 256;

    // 1) init counters + h0
    init_kernel<<<(Hn * Bn + TPB - 1) / TPB, TPB>>>();

    // 2) fused histograms
    dim3 hg((NNZn + TPB - 1) / TPB, 2);
    hist_kernel<<<hg, TPB>>>(hh_idx, ih_idx);

    // 3) hierarchical scans -> rowptr + cursor (both matrices at once)
    dim3 sg(NB, 2);
    scan1_kernel<<<sg, 256>>>();
    scan2_kernel<<<dim3(1, 2), 256>>>();
    scan3_kernel<<<sg, 256>>>();

    // 4) fused scatter into CSR pair arrays
    scatter_kernel<<<hg, TPB>>>(hh_idx, hh_vals, ih_idx, ih_vals);

    // 5) transpose x -> (T, IN, B)
    transpose_kernel<<<(Tn * INn + TPB - 1) / TPB, TPB>>>(x);

    // 6) all 32 input-path spmms in parallel (+ bias folded in)
    ih_kernel<<<(Hn + 31) / 32, TPB>>>(hh_bias);

    // 7) sequential recurrence: 32 single-wave fused spmm+tanh steps
    for (int t = 0; t < Tn; ++t) {
        const float* hprev = h_p + (size_t)(t & 1) * Hn * Bn;
        float*       hnext = h_p + (size_t)((t + 1) & 1) * Hn * Bn;
        const float* ihp   = ihpre_p + (size_t)t * Hn * Bn;
        float*       outt  = out + (size_t)t * Hn;
        if (t + 1 < Tn)
            step_kernel<false><<<STEP_GRID, 256>>>(hprev, hnext, ihp, outt);
        else
            step_kernel<true><<<STEP_GRID, 256>>>(hprev, hnext, ihp, outt);
    }
}

// round 10
// speedup vs baseline: 1.3946x; 1.3946x over previous
#include <cuda_runtime.h>

// Problem constants (from reference_code)
#define Hn    50000
#define INn   50000
#define NNZn  800000
#define Bn    8
#define Tn    32

#define NB    ((Hn + 255) / 256)   // 196 scan blocks per matrix
#define SP    768                  // smem pair staging capacity per step block

// ---------------- device scratch (static globals; no runtime allocation) ----
__device__ float g_xT[(size_t)Tn * INn * Bn];      // x transposed -> (T, IN, B)
__device__ float g_ihpre[(size_t)Tn * Hn * Bn];    // ih spmm + bias, (T, H, B)
__device__ float g_h[2][Hn * Bn];                  // ping-pong hidden state (H, B)
__device__ int   g_rowptr[2][Hn + 1];              // [0]=hh, [1]=ih
__device__ int   g_cnt[2][Hn];
__device__ int   g_cur[2][Hn];
__device__ int   g_bsum[2][256];
__device__ int2  g_pairs[2][NNZn];                 // {col, float_as_int(val)}

// ---------------- preprocessing -------------------------------------------

__global__ void init_kernel() {
    int i = blockIdx.x * blockDim.x + threadIdx.x;
    if (i < Hn * Bn) g_h[0][i] = 0.0f;
    if (i < Hn) { g_cnt[0][i] = 0; g_cnt[1][i] = 0; }
}

// fused histogram over both matrices (gridDim.y selects matrix)
__global__ void hist_kernel(const int* __restrict__ hh_idx,
                            const int* __restrict__ ih_idx) {
    int j = blockIdx.x * blockDim.x + threadIdx.x;
    int m = blockIdx.y;
    if (j >= NNZn) return;
    const int* rows = m ? ih_idx : hh_idx;
    atomicAdd(&g_cnt[m][rows[j]], 1);
}

// phase 1: per-block inclusive scan of 256 counts
__global__ void scan1_kernel() {
    int m = blockIdx.y;
    int i = blockIdx.x * 256 + threadIdx.x;
    int v = (i < Hn) ? g_cnt[m][i] : 0;
    int lane = threadIdx.x & 31, w = threadIdx.x >> 5;
    int x = v;
#pragma unroll
    for (int o = 1; o < 32; o <<= 1) {
        int y = __shfl_up_sync(~0u, x, o);
        if (lane >= o) x += y;
    }
    __shared__ int wsum[8];
    if (lane == 31) wsum[w] = x;
    __syncthreads();
    if (w == 0 && lane < 8) {
        int y = wsum[lane];
#pragma unroll
        for (int o = 1; o < 8; o <<= 1) {
            int z = __shfl_up_sync(0xffu, y, o);
            if (lane >= o) y += z;
        }
        wsum[lane] = y;
    }
    __syncthreads();
    int incl = x + (w > 0 ? wsum[w - 1] : 0);
    if (i < Hn) g_rowptr[m][i] = incl - v;          // local exclusive
    if (threadIdx.x == 255) g_bsum[m][blockIdx.x] = incl;
}

// phase 2: scan the (<=256) block sums
__global__ void scan2_kernel() {
    int m = blockIdx.y;
    int t = threadIdx.x;
    int v = (t < NB) ? g_bsum[m][t] : 0;
    int lane = t & 31, w = t >> 5;
    int x = v;
#pragma unroll
    for (int o = 1; o < 32; o <<= 1) {
        int y = __shfl_up_sync(~0u, x, o);
        if (lane >= o) x += y;
    }
    __shared__ int wsum[8];
    if (lane == 31) wsum[w] = x;
    __syncthreads();
    if (w == 0 && lane < 8) {
        int y = wsum[lane];
#pragma unroll
        for (int o = 1; o < 8; o <<= 1) {
            int z = __shfl_up_sync(0xffu, y, o);
            if (lane >= o) y += z;
        }
        wsum[lane] = y;
    }
    __syncthreads();
    int incl = x + (w > 0 ? wsum[w - 1] : 0);
    if (t < NB) g_bsum[m][t] = incl - v;
    if (t == 255) g_rowptr[m][Hn] = incl;           // total nnz
}

// phase 3: add block offsets; materialize rowptr + scatter cursor
__global__ void scan3_kernel() {
    int m = blockIdx.y;
    int i = blockIdx.x * 256 + threadIdx.x;
    if (i >= Hn) return;
    int r = g_rowptr[m][i] + g_bsum[m][blockIdx.x];
    g_rowptr[m][i] = r;
    g_cur[m][i]    = r;
}

// fused scatter into CSR pair arrays (gridDim.y selects matrix)
__global__ void scatter_kernel(const int* __restrict__ hh_idx,
                               const float* __restrict__ hh_vals,
                               const int* __restrict__ ih_idx,
                               const float* __restrict__ ih_vals) {
    int j = blockIdx.x * blockDim.x + threadIdx.x;
    int m = blockIdx.y;
    if (j >= NNZn) return;
    const int*   idx  = m ? ih_idx  : hh_idx;
    const float* vals = m ? ih_vals : hh_vals;
    int r = idx[j];
    int c = idx[NNZn + j];
    int p = atomicAdd(&g_cur[m][r], 1);
    g_pairs[m][p] = make_int2(c, __float_as_int(vals[j]));
}

// x (B, T, IN) -> g_xT (T, IN, B)
__global__ void transpose_kernel(const float* __restrict__ x) {
    int idx = blockIdx.x * blockDim.x + threadIdx.x;   // over T*IN
    if (idx >= Tn * INn) return;
    int t = idx / INn;
    int c = idx - t * INn;
    float v[Bn];
#pragma unroll
    for (int b = 0; b < Bn; ++b)
        v[b] = x[(size_t)b * Tn * INn + (size_t)t * INn + c];
    float4* dst = reinterpret_cast<float4*>(&g_xT[(size_t)idx * Bn]);
    dst[0] = make_float4(v[0], v[1], v[2], v[3]);
    dst[1] = make_float4(v[4], v[5], v[6], v[7]);
}

// ---------------- main compute ---------------------------------------------

// ih_pre[t, r, b] = bias[r] + sum_j ih_val[j] * xT[t, col[j], b]
// 8 threads per row task (thread = batch lane); all 32 timesteps accumulated
// in registers so each CSR pair is read exactly once. (At its L2 roofline.)
__global__ void ih_kernel(const float* __restrict__ bias) {
    int g = blockIdx.x * 32 + (threadIdx.x >> 3);      // row
    if (g >= Hn) return;
    int b = threadIdx.x & 7;
    float bv = bias[g];
    float acc[Tn];
#pragma unroll
    for (int t = 0; t < Tn; ++t) acc[t] = bv;
    int jb = g_rowptr[1][g];
    int je = g_rowptr[1][g + 1];
    for (int j = jb; j < je; ++j) {
        int2 p = g_pairs[1][j];
        float v = __int_as_float(p.y);
        const float* xp = g_xT + (size_t)p.x * Bn + b;
#pragma unroll
        for (int t = 0; t < Tn; ++t)
            acc[t] += v * xp[(size_t)t * INn * Bn];
    }
#pragma unroll
    for (int t = 0; t < Tn; ++t)
        g_ihpre[((size_t)t * Hn + g) * Bn + b] = acc[t];
}

// one recurrence step (R2 champion layout: 32 rows/block, 8 threads/row),
// with PDL: the h-independent prologue (pair staging into SMEM, ihpre/rowptr
// loads) runs BEFORE cudaGridDependencySynchronize(), overlapping the
// previous step's tail. Upstream triggers right after hnext is written.
template <bool LAST>
__global__ void __launch_bounds__(256)
step_kernel(const float* __restrict__ hprev,
            float* __restrict__ hnext,
            const float* __restrict__ ihpre_t,
            float* __restrict__ out_t) {   // d_out + t*H
    __shared__ int2 s_pairs[SP];

    const int g = blockIdx.x * 32 + (threadIdx.x >> 3);
    const int b = threadIdx.x & 7;
    const bool valid = g < Hn;

    // ---- h-independent prologue ----
    const int row0 = blockIdx.x * 32;
    const int row1 = (row0 + 32 < Hn) ? row0 + 32 : Hn;
    const int base = g_rowptr[0][row0];
    const int nnzb = g_rowptr[0][row1] - base;
    const int stage = nnzb < SP ? nnzb : SP;
    for (int i = threadIdx.x; i < stage; i += 256)
        s_pairs[i] = g_pairs[0][base + i];

    float acc = 0.0f;
    int jb = 0, je = 0;
    if (valid) {
        acc = ihpre_t[g * Bn + b];
        jb = g_rowptr[0][g];
        je = g_rowptr[0][g + 1];
    }
    __syncthreads();

    // ---- wait for upstream step's hnext writes ----
    cudaGridDependencySynchronize();

    float hv = 0.0f;
    if (valid) {
        for (int j = jb; j < je; ++j) {
            int lj = j - base;
            int2 p = (lj < SP) ? s_pairs[lj] : g_pairs[0][j];
            acc += __int_as_float(p.y) * hprev[p.x * Bn + b];
        }
        hv = tanhf(acc);
        if (!LAST) hnext[g * Bn + b] = hv;
    }

    // allow the next step to launch; out is never read downstream
    cudaTriggerProgrammaticLaunchCompletion();

    if (valid)
        out_t[(size_t)b * Tn * Hn + g] = hv;   // out layout (B, T, H)
}

// ---------------- launch ----------------------------------------------------

extern "C" void kernel_launch(void* const* d_in, const int* in_sizes, int n_in,
                              void* d_out, int out_size) {
    const float* x        = (const float*)d_in[0];   // (B, T, IN)
    const float* hh_vals  = (const float*)d_in[1];   // (NNZ,)
    const float* hh_bias  = (const float*)d_in[2];   // (H, 1)
    const float* ih_vals  = (const float*)d_in[3];   // (NNZ,)
    const int*   hh_idx   = (const int*)d_in[4];     // (2, NNZ): rows then cols
    const int*   ih_idx   = (const int*)d_in[5];     // (2, NNZ)
    float*       out      = (float*)d_out;           // (B, T, H)

    float *ihpre_p, *h_p;
    cudaGetSymbolAddress((void**)&ihpre_p, g_ihpre);
    cudaGetSymbolAddress((void**)&h_p,     g_h);

    const int TPB = 256;

    // 1) init counters + h0
    init_kernel<<<(Hn * Bn + TPB - 1) / TPB, TPB>>>();

    // 2) fused histograms
    dim3 hg((NNZn + TPB - 1) / TPB, 2);
    hist_kernel<<<hg, TPB>>>(hh_idx, ih_idx);

    // 3) hierarchical scans -> rowptr + cursor (both matrices at once)
    dim3 sg(NB, 2);
    scan1_kernel<<<sg, 256>>>();
    scan2_kernel<<<dim3(1, 2), 256>>>();
    scan3_kernel<<<sg, 256>>>();

    // 4) fused scatter into CSR pair arrays
    scatter_kernel<<<hg, TPB>>>(hh_idx, hh_vals, ih_idx, ih_vals);

    // 5) transpose x -> (T, IN, B)
    transpose_kernel<<<(Tn * INn + TPB - 1) / TPB, TPB>>>(x);

    // 6) all 32 input-path spmms in parallel (+ bias folded in)
    ih_kernel<<<(Hn + 31) / 32, TPB>>>(hh_bias);

    // 7) sequential recurrence: 32 steps chained with programmatic launches
    const int step_grid = (Hn + 31) / 32;        // 1563 blocks (R2 champion)

    cudaLaunchAttribute attrs[1];
    attrs[0].id = cudaLaunchAttributeProgrammaticStreamSerialization;
    attrs[0].val.programmaticStreamSerializationAllowed = 1;

    cudaLaunchConfig_t cfg = {};
    cfg.gridDim  = dim3(step_grid, 1, 1);
    cfg.blockDim = dim3(256, 1, 1);
    cfg.dynamicSmemBytes = 0;
    cfg.stream = 0;                              // legacy default stream
    cfg.attrs = attrs;
    cfg.numAttrs = 1;

    for (int t = 0; t < Tn; ++t) {
        const float* hprev = h_p + (size_t)(t & 1) * Hn * Bn;
        float*       hnext = h_p + (size_t)((t + 1) & 1) * Hn * Bn;
        const float* ihp   = ihpre_p + (size_t)t * Hn * Bn;
        float*       outt  = out + (size_t)t * Hn;
        if (t + 1 < Tn)
            cudaLaunchKernelEx(&cfg, step_kernel<false>, hprev, hnext, ihp, outt);
        else
            cudaLaunchKernelEx(&cfg, step_kernel<true>,  hprev, hnext, ihp, outt);
    }
}